// round 6
// baseline (speedup 1.0000x reference)
#include <cuda_runtime.h>

#define NMAX 50000
#define EMAX 800000
#define HC   128
#define FIN  64

// ---------------- scratch (static device arrays; no allocation) ----------------
__device__ float h_g[NMAX * HC];        // x @ W                [N,128]
__device__ float res_g[NMAX * HC];      // x @ res_w + res_b    [N,128]
__device__ float a_src_g[NMAX * 4];     // per-head src coeff   [N,4]
__device__ float a_dst_g[NMAX * 4];     // per-head dst coeff   [N,4]
__device__ int   deg_g[NMAX];
__device__ int   rowptr_g[NMAX + 1];
__device__ int   rowcur_g[NMAX];
__device__ int   col_g[EMAX];
__device__ int   src_g[EMAX];
__device__ int   dst_g[EMAX];
__device__ int   is64_g;

#define LEAKY(v) ((v) >= 0.f ? (v) : 0.2f * (v))

// ---------------- packed f32x2 helpers ----------------
__device__ __forceinline__ unsigned long long pack2(float a, float b)
{
    unsigned long long r;
    asm("mov.b64 %0, {%1, %2};" : "=l"(r) : "f"(a), "f"(b));
    return r;
}
__device__ __forceinline__ void unpack2(unsigned long long v, float& a, float& b)
{
    asm("mov.b64 {%0, %1}, %2;" : "=f"(a), "=f"(b) : "l"(v));
}
__device__ __forceinline__ void fma2(unsigned long long& d, unsigned long long a, unsigned long long b)
{
    asm("fma.rn.f32x2 %0, %1, %2, %0;" : "+l"(d) : "l"(a), "l"(b));
}

// ---------------- zero degrees + edge dtype detection (int32 vs int64) --------
__global__ void prep_kernel(const int* __restrict__ raw, int n, int E)
{
    int i = blockIdx.x * blockDim.x + threadIdx.x;
    if (i < n) deg_g[i] = 0;
    if (blockIdx.x == 0) {
        __shared__ int any_nonzero;
        if (threadIdx.x == 0) any_nonzero = 0;
        __syncthreads();
        int nwords = 1024;
        if (nwords > 2 * E) nwords = 2 * E;
        for (int j = threadIdx.x; j < nwords / 2; j += blockDim.x)
            if (raw[2 * j + 1] != 0) any_nonzero = 1;
        __syncthreads();
        if (threadIdx.x == 0) is64_g = any_nonzero ? 0 : 1;
    }
}

// ---------------- extract src/dst + histogram (4 edges/thread, MLP=4) ---------
__global__ void extract_hist_kernel(const void* __restrict__ raw, int E, int T)
{
    int t = blockIdx.x * blockDim.x + threadIdx.x;
    if (t >= T) return;   // guard: each edge handled by exactly one thread slot
    int i0 = t, i1 = t + T, i2 = t + 2 * T, i3 = t + 3 * T;
    int s0, s1, s2, s3, d0, d1, d2, d3;
    if (is64_g) {
        const long long* p = (const long long*)raw;
        if (i0 < E) { s0 = (int)p[i0]; d0 = (int)p[E + i0]; }
        if (i1 < E) { s1 = (int)p[i1]; d1 = (int)p[E + i1]; }
        if (i2 < E) { s2 = (int)p[i2]; d2 = (int)p[E + i2]; }
        if (i3 < E) { s3 = (int)p[i3]; d3 = (int)p[E + i3]; }
    } else {
        const int* p = (const int*)raw;
        if (i0 < E) { s0 = p[i0]; d0 = p[E + i0]; }
        if (i1 < E) { s1 = p[i1]; d1 = p[E + i1]; }
        if (i2 < E) { s2 = p[i2]; d2 = p[E + i2]; }
        if (i3 < E) { s3 = p[i3]; d3 = p[E + i3]; }
    }
    if (i0 < E) { src_g[i0] = s0; dst_g[i0] = d0; atomicAdd(&deg_g[d0], 1); }
    if (i1 < E) { src_g[i1] = s1; dst_g[i1] = d1; atomicAdd(&deg_g[d1], 1); }
    if (i2 < E) { src_g[i2] = s2; dst_g[i2] = d2; atomicAdd(&deg_g[d2], 1); }
    if (i3 < E) { src_g[i3] = s3; dst_g[i3] = d3; atomicAdd(&deg_g[d3], 1); }
}

// ---------------- single-block scan over N ----------------
__global__ void scan_kernel(int n)
{
    __shared__ int sh[1024];
    int t = threadIdx.x;
    int chunk = (n + 1023) >> 10;
    int s0 = t * chunk;
    int s1 = s0 + chunk;
    if (s0 > n) s0 = n;
    if (s1 > n) s1 = n;
    int s = 0;
#pragma unroll 4
    for (int i = s0; i < s1; i++) s += deg_g[i];
    sh[t] = s;
    __syncthreads();
#pragma unroll
    for (int off = 1; off < 1024; off <<= 1) {
        int v = (t >= off) ? sh[t - off] : 0;
        __syncthreads();
        sh[t] += v;
        __syncthreads();
    }
    int run = sh[t] - s;  // exclusive prefix
    for (int i = s0; i < s1; i++) {
        rowptr_g[i] = run;
        rowcur_g[i] = run;
        run += deg_g[i];
    }
    if (t == 1023) rowptr_g[n] = sh[1023];
}

// ---------------- scatter (4 edges/thread, MLP=4) ----------------
__global__ void scatter_kernel(int E, int T)
{
    int t = blockIdx.x * blockDim.x + threadIdx.x;
    if (t >= T) return;   // guard: each edge handled by exactly one thread slot
    int i0 = t, i1 = t + T, i2 = t + 2 * T, i3 = t + 3 * T;
    int d0, d1, d2, d3, s0, s1, s2, s3;
    if (i0 < E) { d0 = dst_g[i0]; s0 = src_g[i0]; }
    if (i1 < E) { d1 = dst_g[i1]; s1 = src_g[i1]; }
    if (i2 < E) { d2 = dst_g[i2]; s2 = src_g[i2]; }
    if (i3 < E) { d3 = dst_g[i3]; s3 = src_g[i3]; }
    int p0, p1, p2, p3;
    if (i0 < E) p0 = atomicAdd(&rowcur_g[d0], 1);
    if (i1 < E) p1 = atomicAdd(&rowcur_g[d1], 1);
    if (i2 < E) p2 = atomicAdd(&rowcur_g[d2], 1);
    if (i3 < E) p3 = atomicAdd(&rowcur_g[d3], 1);
    if (i0 < E) col_g[p0] = s0;
    if (i1 < E) col_g[p1] = s1;
    if (i2 < E) col_g[p2] = s2;
    if (i3 < E) col_g[p3] = s3;
}

// ---------------- fused GEMM (f32x2 packed): h, res, att coeffs ---------------
// 256 threads. Warp lanes = 32 nodes; warp w covers cols [w*32, w*32+32).
// Warps 0..3 produce h (head = wid) + per-head attention dots.
__global__ void gemm_kernel(const float* __restrict__ x, const float* __restrict__ W,
                            const float* __restrict__ Rw, const float* __restrict__ Rb,
                            const float* __restrict__ att_s, const float* __restrict__ att_d,
                            int n, int ntiles)
{
    extern __shared__ float smem[];
    float* Wsh = smem;                     // [64][256]
    float* xsh = smem + FIN * 256;         // [32][65] padded
    float* asl = xsh + 32 * 65;            // [128] att_src
    float* adl = asl + 128;                // [128] att_dst

    int t = threadIdx.x;
    for (int i = t; i < FIN * 256; i += 256) {
        int c = i & 255;
        int k = i >> 8;
        Wsh[i] = (c < 128) ? W[k * 128 + c] : Rw[k * 128 + (c - 128)];
    }
    if (t < 128) {
        asl[t] = att_s[t];
        adl[t] = att_d[t];
    }
    __syncthreads();

    int lane = t & 31, wid = t >> 5;

    for (int tile = blockIdx.x; tile < ntiles; tile += gridDim.x) {
        int n0 = tile << 5;
        for (int i = t; i < 32 * FIN; i += 256) {
            int r = i >> 6, k = i & 63;
            int node = n0 + r;
            xsh[r * 65 + k] = (node < n) ? x[node * FIN + k] : 0.f;
        }
        __syncthreads();

        unsigned long long acc2[16];
        unsigned long long z = pack2(0.f, 0.f);
#pragma unroll
        for (int q = 0; q < 16; q++) acc2[q] = z;

#pragma unroll 4
        for (int k = 0; k < FIN; k++) {
            float xv = xsh[lane * 65 + k];
            unsigned long long xx = pack2(xv, xv);
            const unsigned long long* wrow = (const unsigned long long*)&Wsh[k * 256 + wid * 32];
#pragma unroll
            for (int q = 0; q < 16; q++) fma2(acc2[q], xx, wrow[q]);
        }

        float acc[32];
#pragma unroll
        for (int q = 0; q < 16; q++) unpack2(acc2[q], acc[2 * q], acc[2 * q + 1]);

        int node = n0 + lane;
        if (node < n) {
            if (wid < 4) {
                float4* hp = (float4*)&h_g[node * HC + wid * 32];
#pragma unroll
                for (int q = 0; q < 8; q++)
                    hp[q] = make_float4(acc[q * 4], acc[q * 4 + 1], acc[q * 4 + 2], acc[q * 4 + 3]);
                // attention dots for head = wid (broadcast smem reads)
                float ss = 0.f, sd = 0.f;
#pragma unroll
                for (int c = 0; c < 32; c++) {
                    ss += acc[c] * asl[wid * 32 + c];
                    sd += acc[c] * adl[wid * 32 + c];
                }
                a_src_g[node * 4 + wid] = ss;
                a_dst_g[node * 4 + wid] = sd;
            } else {
                int c0 = (wid - 4) * 32;
                float4* rp = (float4*)&res_g[node * HC + c0];
                const float4* bp = (const float4*)&Rb[c0];
#pragma unroll
                for (int q = 0; q < 8; q++) {
                    float4 b = bp[q];
                    rp[q] = make_float4(acc[q * 4] + b.x, acc[q * 4 + 1] + b.y,
                                        acc[q * 4 + 2] + b.z, acc[q * 4 + 3] + b.w);
                }
            }
        }
        __syncthreads();
    }
}

// ---------------- fused aggregate + softmax + ELU + residual + LayerNorm ------
// One warp per destination node. Lane l holds channels [4l,4l+4), head = l/8.
// No max subtraction: e ~ N(0,1), exp safe in fp32; softmax identical.
__global__ void aggregate_kernel(const float* __restrict__ bias,
                                 const float* __restrict__ lng, const float* __restrict__ lnb,
                                 float* __restrict__ out, int n)
{
    int warp = (blockIdx.x * blockDim.x + threadIdx.x) >> 5;
    int lane = threadIdx.x & 31;
    if (warp >= n) return;
    int v = warp;
    int head = lane >> 3;

    float adh = a_dst_g[v * 4 + head];
    const float4* hp = (const float4*)h_g;

    // self loop
    float w0 = __expf(LEAKY(a_src_g[v * 4 + head] + adh));
    float4 hv = hp[v * 32 + lane];
    float4 acc = make_float4(w0 * hv.x, w0 * hv.y, w0 * hv.z, w0 * hv.w);
    float dsum = w0;

    int rs = rowptr_g[v], re = rowptr_g[v + 1];
    int i = rs;
    // 8x unrolled: batch index loads -> batch coeff loads -> batch row loads (MLP=8)
    for (; i + 8 <= re; i += 8) {
        int u[8];
#pragma unroll
        for (int q = 0; q < 8; q++) u[q] = col_g[i + q];
        float e[8];
#pragma unroll
        for (int q = 0; q < 8; q++) e[q] = a_src_g[u[q] * 4 + head];
        float4 hr[8];
#pragma unroll
        for (int q = 0; q < 8; q++) hr[q] = hp[u[q] * 32 + lane];
#pragma unroll
        for (int q = 0; q < 8; q++) {
            float wv = __expf(LEAKY(e[q] + adh));
            acc.x += wv * hr[q].x;
            acc.y += wv * hr[q].y;
            acc.z += wv * hr[q].z;
            acc.w += wv * hr[q].w;
            dsum += wv;
        }
    }
    for (; i + 4 <= re; i += 4) {
        int u0 = col_g[i], u1 = col_g[i + 1], u2 = col_g[i + 2], u3 = col_g[i + 3];
        float e0 = a_src_g[u0 * 4 + head];
        float e1 = a_src_g[u1 * 4 + head];
        float e2 = a_src_g[u2 * 4 + head];
        float e3 = a_src_g[u3 * 4 + head];
        float4 h0 = hp[u0 * 32 + lane];
        float4 h1 = hp[u1 * 32 + lane];
        float4 h2 = hp[u2 * 32 + lane];
        float4 h3 = hp[u3 * 32 + lane];
        float x0 = __expf(LEAKY(e0 + adh));
        float x1 = __expf(LEAKY(e1 + adh));
        float x2 = __expf(LEAKY(e2 + adh));
        float x3 = __expf(LEAKY(e3 + adh));
        acc.x += x0 * h0.x + x1 * h1.x + x2 * h2.x + x3 * h3.x;
        acc.y += x0 * h0.y + x1 * h1.y + x2 * h2.y + x3 * h3.y;
        acc.z += x0 * h0.z + x1 * h1.z + x2 * h2.z + x3 * h3.z;
        acc.w += x0 * h0.w + x1 * h1.w + x2 * h2.w + x3 * h3.w;
        dsum += x0 + x1 + x2 + x3;
    }
    for (; i < re; i++) {
        int u = col_g[i];
        float wv = __expf(LEAKY(a_src_g[u * 4 + head] + adh));
        float4 hu = hp[u * 32 + lane];
        acc.x += wv * hu.x;
        acc.y += wv * hu.y;
        acc.z += wv * hu.z;
        acc.w += wv * hu.w;
        dsum += wv;
    }

    float inv = 1.f / dsum;
    float4 b = ((const float4*)bias)[lane];
    float4 o;
    o.x = acc.x * inv + b.x;
    o.y = acc.y * inv + b.y;
    o.z = acc.z * inv + b.z;
    o.w = acc.w * inv + b.w;

    // ELU
    o.x = o.x > 0.f ? o.x : expm1f(o.x);
    o.y = o.y > 0.f ? o.y : expm1f(o.y);
    o.z = o.z > 0.f ? o.z : expm1f(o.z);
    o.w = o.w > 0.f ? o.w : expm1f(o.w);

    // residual
    float4 r = ((const float4*)res_g)[v * 32 + lane];
    o.x += r.x; o.y += r.y; o.z += r.z; o.w += r.w;

    // LayerNorm over 128 (warp-wide)
    float s = o.x + o.y + o.z + o.w;
#pragma unroll
    for (int off = 16; off; off >>= 1) s += __shfl_xor_sync(0xffffffffu, s, off);
    float mean = s * (1.f / 128.f);

    float cx = o.x - mean, cy = o.y - mean, cz = o.z - mean, cw = o.w - mean;
    float sq = cx * cx + cy * cy + cz * cz + cw * cw;
#pragma unroll
    for (int off = 16; off; off >>= 1) sq += __shfl_xor_sync(0xffffffffu, sq, off);
    float rinv = rsqrtf(sq * (1.f / 128.f) + 1e-5f);

    float4 g  = ((const float4*)lng)[lane];
    float4 lb = ((const float4*)lnb)[lane];
    float4 oo;
    oo.x = cx * rinv * g.x + lb.x;
    oo.y = cy * rinv * g.y + lb.y;
    oo.z = cz * rinv * g.z + lb.z;
    oo.w = cw * rinv * g.w + lb.w;

    ((float4*)out)[v * 32 + lane] = oo;
}

// ---------------- launch (fork-join: CSR build overlaps GEMM) ----------------
extern "C" void kernel_launch(void* const* d_in, const int* in_sizes, int n_in,
                              void* d_out, int out_size)
{
    const float* x     = (const float*)d_in[0];
    const void*  ei    = d_in[1];
    const float* W     = (const float*)d_in[2];
    const float* att_s = (const float*)d_in[3];
    const float* att_d = (const float*)d_in[4];
    const float* bias  = (const float*)d_in[5];
    const float* Rw    = (const float*)d_in[6];
    const float* Rb    = (const float*)d_in[7];
    const float* lng   = (const float*)d_in[8];
    const float* lnb   = (const float*)d_in[9];

    int n = in_sizes[0] / FIN;
    int E = in_sizes[1] / 2;
    int ntiles = (n + 31) / 32;
    int T = (E + 3) / 4;   // threads for 4-way edge kernels

    static cudaStream_t s2 = 0;
    static cudaEvent_t evFork = 0, evJoin = 0;
    static int inited = 0;
    int gemm_smem = (FIN * 256 + 32 * 65 + 256) * (int)sizeof(float);
    if (!inited) {
        cudaFuncSetAttribute(gemm_kernel, cudaFuncAttributeMaxDynamicSharedMemorySize, gemm_smem);
        cudaStreamCreateWithFlags(&s2, cudaStreamNonBlocking);
        cudaEventCreateWithFlags(&evFork, cudaEventDisableTiming);
        cudaEventCreateWithFlags(&evJoin, cudaEventDisableTiming);
        inited = 1;
    }

    // fork: s2 does the CSR build while stream 0 does the GEMM
    cudaEventRecord(evFork, 0);
    cudaStreamWaitEvent(s2, evFork, 0);

    prep_kernel<<<(n + 255) / 256, 256, 0, s2>>>((const int*)ei, n, E);
    extract_hist_kernel<<<(T + 255) / 256, 256, 0, s2>>>(ei, E, T);
    scan_kernel<<<1, 1024, 0, s2>>>(n);
    scatter_kernel<<<(T + 255) / 256, 256, 0, s2>>>(E, T);
    cudaEventRecord(evJoin, s2);

    gemm_kernel<<<444, 256, gemm_smem>>>(x, W, Rw, Rb, att_s, att_d, n, ntiles);

    // join
    cudaStreamWaitEvent(0, evJoin, 0);
    aggregate_kernel<<<(n + 7) / 8, 256>>>(bias, lng, lnb, (float*)d_out, n);
}

// round 7
// speedup vs baseline: 1.5905x; 1.5905x over previous
#include <cuda_runtime.h>

#define NMAX 50000
#define EMAX 800000
#define HC   128
#define FIN  64

// ---------------- scratch (static device arrays; no allocation) ----------------
__device__ float h_g[NMAX * HC];        // x @ W                [N,128]
__device__ float res_g[NMAX * HC];      // x @ res_w + res_b    [N,128]
__device__ float a_src_g[NMAX * 4];     // per-head src coeff   [N,4]
__device__ float a_dst_g[NMAX * 4];     // per-head dst coeff   [N,4]
__device__ int   deg_g[NMAX];
__device__ int   rowptr_g[NMAX + 1];
__device__ int   rowcur_g[NMAX];
__device__ int   col_g[EMAX];
__device__ int   src_g[EMAX];
__device__ int   dst_g[EMAX];
__device__ int   is64_g;

#define LEAKY(v) ((v) >= 0.f ? (v) : 0.2f * (v))

// ---------------- zero degrees + edge dtype detection (int32 vs int64) --------
__global__ void prep_kernel(const int* __restrict__ raw, int n, int E)
{
    int i = blockIdx.x * blockDim.x + threadIdx.x;
    if (i < n) deg_g[i] = 0;
    if (blockIdx.x == 0) {
        __shared__ int any_nonzero;
        if (threadIdx.x == 0) any_nonzero = 0;
        __syncthreads();
        int nwords = 1024;
        if (nwords > 2 * E) nwords = 2 * E;
        for (int j = threadIdx.x; j < nwords / 2; j += blockDim.x)
            if (raw[2 * j + 1] != 0) any_nonzero = 1;
        __syncthreads();
        if (threadIdx.x == 0) is64_g = any_nonzero ? 0 : 1;
    }
}

// ---------------- extract src/dst + histogram destinations ----------------
__global__ void extract_hist_kernel(const void* __restrict__ raw, int E)
{
    int i = blockIdx.x * blockDim.x + threadIdx.x;
    if (i >= E) return;
    int s, d;
    if (is64_g) {
        const long long* p = (const long long*)raw;
        s = (int)p[i];
        d = (int)p[E + i];
    } else {
        const int* p = (const int*)raw;
        s = p[i];
        d = p[E + i];
    }
    src_g[i] = s;
    dst_g[i] = d;
    atomicAdd(&deg_g[d], 1);
}

// ---------------- single-block scan over N ----------------
__global__ void scan_kernel(int n)
{
    __shared__ int sh[1024];
    int t = threadIdx.x;
    int chunk = (n + 1023) >> 10;
    int s0 = t * chunk;
    int s1 = s0 + chunk;
    if (s0 > n) s0 = n;
    if (s1 > n) s1 = n;
    int s = 0;
#pragma unroll 4
    for (int i = s0; i < s1; i++) s += deg_g[i];
    sh[t] = s;
    __syncthreads();
#pragma unroll
    for (int off = 1; off < 1024; off <<= 1) {
        int v = (t >= off) ? sh[t - off] : 0;
        __syncthreads();
        sh[t] += v;
        __syncthreads();
    }
    int run = sh[t] - s;  // exclusive prefix
    for (int i = s0; i < s1; i++) {
        rowptr_g[i] = run;
        rowcur_g[i] = run;
        run += deg_g[i];
    }
    if (t == 1023) rowptr_g[n] = sh[1023];
}

__global__ void scatter_kernel(int E)
{
    int i = blockIdx.x * blockDim.x + threadIdx.x;
    if (i >= E) return;
    int p = atomicAdd(&rowcur_g[dst_g[i]], 1);
    col_g[p] = src_g[i];
}

// ---------------- fused GEMM: h = x@W ; res = x@res_w + res_b ; att coeffs ----
// 256 threads. Warp lanes = 32 nodes; warp w covers cols [w*32, w*32+32).
// Warps 0..3 produce h (head = wid) and the per-head attention dots.
__global__ void gemm_kernel(const float* __restrict__ x, const float* __restrict__ W,
                            const float* __restrict__ Rw, const float* __restrict__ Rb,
                            const float* __restrict__ att_s, const float* __restrict__ att_d,
                            int n, int ntiles)
{
    extern __shared__ float smem[];
    float* Wsh = smem;                     // [64][256]
    float* xsh = smem + FIN * 256;         // [32][65] padded
    float* asl = xsh + 32 * 65;            // [128] att_src
    float* adl = asl + 128;                // [128] att_dst

    int t = threadIdx.x;
    for (int i = t; i < FIN * 256; i += 256) {
        int c = i & 255;
        int k = i >> 8;
        Wsh[i] = (c < 128) ? W[k * 128 + c] : Rw[k * 128 + (c - 128)];
    }
    if (t < 128) {
        asl[t] = att_s[t];
        adl[t] = att_d[t];
    }
    __syncthreads();

    int lane = t & 31, wid = t >> 5;

    for (int tile = blockIdx.x; tile < ntiles; tile += gridDim.x) {
        int n0 = tile << 5;
        for (int i = t; i < 32 * FIN; i += 256) {
            int r = i >> 6, k = i & 63;
            int node = n0 + r;
            xsh[r * 65 + k] = (node < n) ? x[node * FIN + k] : 0.f;
        }
        __syncthreads();

        float acc[32];
#pragma unroll
        for (int q = 0; q < 32; q++) acc[q] = 0.f;

#pragma unroll 4
        for (int k = 0; k < FIN; k++) {
            float xv = xsh[lane * 65 + k];
            const float4* wrow = (const float4*)&Wsh[k * 256 + wid * 32];
#pragma unroll
            for (int q = 0; q < 8; q++) {
                float4 wv = wrow[q];
                acc[q * 4 + 0] += xv * wv.x;
                acc[q * 4 + 1] += xv * wv.y;
                acc[q * 4 + 2] += xv * wv.z;
                acc[q * 4 + 3] += xv * wv.w;
            }
        }

        int node = n0 + lane;
        if (node < n) {
            if (wid < 4) {
                float4* hp = (float4*)&h_g[node * HC + wid * 32];
#pragma unroll
                for (int q = 0; q < 8; q++)
                    hp[q] = make_float4(acc[q * 4], acc[q * 4 + 1], acc[q * 4 + 2], acc[q * 4 + 3]);
                // attention dots for head = wid (broadcast smem reads)
                float ss = 0.f, sd = 0.f;
#pragma unroll
                for (int c = 0; c < 32; c++) {
                    ss += acc[c] * asl[wid * 32 + c];
                    sd += acc[c] * adl[wid * 32 + c];
                }
                a_src_g[node * 4 + wid] = ss;
                a_dst_g[node * 4 + wid] = sd;
            } else {
                int c0 = (wid - 4) * 32;
                float4* rp = (float4*)&res_g[node * HC + c0];
                const float4* bp = (const float4*)&Rb[c0];
#pragma unroll
                for (int q = 0; q < 8; q++) {
                    float4 b = bp[q];
                    rp[q] = make_float4(acc[q * 4] + b.x, acc[q * 4 + 1] + b.y,
                                        acc[q * 4 + 2] + b.z, acc[q * 4 + 3] + b.w);
                }
            }
        }
        __syncthreads();
    }
}

// ---------------- fused aggregate + softmax + ELU + residual + LayerNorm ------
// TWO warps per destination node (even/odd edge interleave) to double MLP
// without register pressure. Lane l holds channels [4l,4l+4), head = l/8.
// Block = 256 threads = 8 warps = 4 nodes. Partials combined via smem.
__global__ __launch_bounds__(256, 4)
void aggregate_kernel(const float* __restrict__ bias,
                      const float* __restrict__ lng, const float* __restrict__ lnb,
                      float* __restrict__ out, int n)
{
    __shared__ float4 pacc[4][32];
    __shared__ float  pd[4][4];

    int tid = threadIdx.x;
    int wid = tid >> 5, lane = tid & 31;
    int nodeIdx = wid >> 1;   // 0..3
    int sub = wid & 1;        // 0: even edges + self loop + epilogue, 1: odd edges
    int v = blockIdx.x * 4 + nodeIdx;
    int head = lane >> 3;

    const float4* hp = (const float4*)h_g;
    float4 acc = make_float4(0.f, 0.f, 0.f, 0.f);
    float dsum = 0.f;

    if (v < n) {
        float adh = a_dst_g[v * 4 + head];

        if (sub == 0) {
            // self loop
            float w0 = __expf(LEAKY(a_src_g[v * 4 + head] + adh));
            float4 hv = hp[v * 32 + lane];
            acc = make_float4(w0 * hv.x, w0 * hv.y, w0 * hv.z, w0 * hv.w);
            dsum = w0;
        }

        int rs = rowptr_g[v], re = rowptr_g[v + 1];
        int i = rs + sub;
        // 4 edges per iteration from this warp's parity class (stride 2)
        for (; i + 6 < re; i += 8) {
            int u0 = col_g[i], u1 = col_g[i + 2], u2 = col_g[i + 4], u3 = col_g[i + 6];
            float e0 = a_src_g[u0 * 4 + head];
            float e1 = a_src_g[u1 * 4 + head];
            float e2 = a_src_g[u2 * 4 + head];
            float e3 = a_src_g[u3 * 4 + head];
            float4 h0 = hp[u0 * 32 + lane];
            float4 h1 = hp[u1 * 32 + lane];
            float4 h2 = hp[u2 * 32 + lane];
            float4 h3 = hp[u3 * 32 + lane];
            float x0 = __expf(LEAKY(e0 + adh));
            float x1 = __expf(LEAKY(e1 + adh));
            float x2 = __expf(LEAKY(e2 + adh));
            float x3 = __expf(LEAKY(e3 + adh));
            acc.x += x0 * h0.x + x1 * h1.x + x2 * h2.x + x3 * h3.x;
            acc.y += x0 * h0.y + x1 * h1.y + x2 * h2.y + x3 * h3.y;
            acc.z += x0 * h0.z + x1 * h1.z + x2 * h2.z + x3 * h3.z;
            acc.w += x0 * h0.w + x1 * h1.w + x2 * h2.w + x3 * h3.w;
            dsum += x0 + x1 + x2 + x3;
        }
        for (; i < re; i += 2) {
            int u = col_g[i];
            float wv = __expf(LEAKY(a_src_g[u * 4 + head] + adh));
            float4 hu = hp[u * 32 + lane];
            acc.x += wv * hu.x;
            acc.y += wv * hu.y;
            acc.z += wv * hu.z;
            acc.w += wv * hu.w;
            dsum += wv;
        }
    }

    if (sub == 1) {
        pacc[nodeIdx][lane] = acc;
        if ((lane & 7) == 0) pd[nodeIdx][head] = dsum;
    }
    __syncthreads();

    if (sub == 0 && v < n) {
        float4 p = pacc[nodeIdx][lane];
        acc.x += p.x; acc.y += p.y; acc.z += p.z; acc.w += p.w;
        dsum += pd[nodeIdx][head];

        float inv = 1.f / dsum;
        float4 b = ((const float4*)bias)[lane];
        float4 o;
        o.x = acc.x * inv + b.x;
        o.y = acc.y * inv + b.y;
        o.z = acc.z * inv + b.z;
        o.w = acc.w * inv + b.w;

        // ELU
        o.x = o.x > 0.f ? o.x : expm1f(o.x);
        o.y = o.y > 0.f ? o.y : expm1f(o.y);
        o.z = o.z > 0.f ? o.z : expm1f(o.z);
        o.w = o.w > 0.f ? o.w : expm1f(o.w);

        // residual
        float4 r = ((const float4*)res_g)[v * 32 + lane];
        o.x += r.x; o.y += r.y; o.z += r.z; o.w += r.w;

        // LayerNorm over 128 (warp-wide)
        float s = o.x + o.y + o.z + o.w;
#pragma unroll
        for (int off = 16; off; off >>= 1) s += __shfl_xor_sync(0xffffffffu, s, off);
        float mean = s * (1.f / 128.f);

        float cx = o.x - mean, cy = o.y - mean, cz = o.z - mean, cw = o.w - mean;
        float sq = cx * cx + cy * cy + cz * cz + cw * cw;
#pragma unroll
        for (int off = 16; off; off >>= 1) sq += __shfl_xor_sync(0xffffffffu, sq, off);
        float rinv = rsqrtf(sq * (1.f / 128.f) + 1e-5f);

        float4 g  = ((const float4*)lng)[lane];
        float4 lb = ((const float4*)lnb)[lane];
        float4 oo;
        oo.x = cx * rinv * g.x + lb.x;
        oo.y = cy * rinv * g.y + lb.y;
        oo.z = cz * rinv * g.z + lb.z;
        oo.w = cw * rinv * g.w + lb.w;

        ((float4*)out)[v * 32 + lane] = oo;
    }
}

// ---------------- launch (fork-join: CSR build overlaps GEMM) ----------------
extern "C" void kernel_launch(void* const* d_in, const int* in_sizes, int n_in,
                              void* d_out, int out_size)
{
    const float* x     = (const float*)d_in[0];
    const void*  ei    = d_in[1];
    const float* W     = (const float*)d_in[2];
    const float* att_s = (const float*)d_in[3];
    const float* att_d = (const float*)d_in[4];
    const float* bias  = (const float*)d_in[5];
    const float* Rw    = (const float*)d_in[6];
    const float* Rb    = (const float*)d_in[7];
    const float* lng   = (const float*)d_in[8];
    const float* lnb   = (const float*)d_in[9];

    int n = in_sizes[0] / FIN;
    int E = in_sizes[1] / 2;
    int ntiles = (n + 31) / 32;

    static cudaStream_t s2 = 0;
    static cudaEvent_t evFork = 0, evJoin = 0;
    static int inited = 0;
    int gemm_smem = (FIN * 256 + 32 * 65 + 256) * (int)sizeof(float);
    if (!inited) {
        cudaFuncSetAttribute(gemm_kernel, cudaFuncAttributeMaxDynamicSharedMemorySize, gemm_smem);
        cudaStreamCreateWithFlags(&s2, cudaStreamNonBlocking);
        cudaEventCreateWithFlags(&evFork, cudaEventDisableTiming);
        cudaEventCreateWithFlags(&evJoin, cudaEventDisableTiming);
        inited = 1;
    }

    // fork: s2 does the CSR build while stream 0 does the GEMM
    cudaEventRecord(evFork, 0);
    cudaStreamWaitEvent(s2, evFork, 0);

    prep_kernel<<<(n + 255) / 256, 256, 0, s2>>>((const int*)ei, n, E);
    extract_hist_kernel<<<(E + 255) / 256, 256, 0, s2>>>(ei, E);
    scan_kernel<<<1, 1024, 0, s2>>>(n);
    scatter_kernel<<<(E + 255) / 256, 256, 0, s2>>>(E);
    cudaEventRecord(evJoin, s2);

    gemm_kernel<<<444, 256, gemm_smem>>>(x, W, Rw, Rb, att_s, att_d, n, ntiles);

    // join
    cudaStreamWaitEvent(0, evJoin, 0);
    aggregate_kernel<<<(n + 3) / 4, 256>>>(bias, lng, lnb, (float*)d_out, n);
}